// round 6
// baseline (speedup 1.0000x reference)
#include <cuda_runtime.h>
#include <math.h>

#define MAX_IN 64
#define D_MODEL 64
#define THREADS 256
#define CHUNK 64          // rows grabbed per block per steal
#define NBLOCKS (148 * 6)

__device__ int g_ctr;

__device__ __forceinline__ float fast_tanh(float x) {
    float y;
    asm("tanh.approx.f32 %0, %1;" : "=f"(y) : "f"(x));
    return y;
}

__device__ __forceinline__ float gelu_tanh(float v) {
    const float c = 0.7978845608028654f;
    float u = c * (v + 0.044715f * v * v * v);
    return 0.5f * v * (1.0f + fast_tanh(u));
}

__global__ void k_reset() { g_ctr = 0; }

__global__ __launch_bounds__(THREADS, 6)
void fe_kernel(const float* __restrict__ seg,
               const float* __restrict__ W,
               const float* __restrict__ b,
               const int*   __restrict__ lengths,
               float* __restrict__ out,
               int n)
{
    __shared__ float sx[CHUNK][MAX_IN];   // 16 KB
    __shared__ int   slen[CHUNK];
    __shared__ int   s_base;
    __shared__ int   s_next;

    const int tid  = threadIdx.x;
    const int lane = tid & 31;
    const unsigned gmask = (lane < 16) ? 0x0000FFFFu : 0xFFFF0000u;
    const int gsrc = lane & 16;          // group leader lane within warp
    const int t    = tid & 15;           // d-chunk (float4 over D_MODEL)

    while (true) {
        if (tid == 0) {
            s_base = atomicAdd(&g_ctr, CHUNK);
            s_next = 0;
        }
        __syncthreads();
        const int base = s_base;
        if (base >= n) break;
        const int cnt = min(CHUNK, n - base);

        // load lengths for this chunk
        if (tid < CHUNK) slen[tid] = (tid < cnt) ? lengths[base + tid] : 0;
        __syncthreads();

        // stage x rows masked into smem: CHUNK*16 float4 = 1024, 4 per thread
        #pragma unroll
        for (int j = 0; j < (CHUNK * 16) / THREADS; ++j) {
            int idx = tid + j * THREADS;
            int r   = idx >> 4;
            int c4  = idx & 15;
            float4 v = make_float4(0.f, 0.f, 0.f, 0.f);
            int len = slen[r];
            if (len > 0) {
                v = reinterpret_cast<const float4*>(seg)[(size_t)(base + r) * 16 + c4];
                int c = c4 * 4;
                if (c + 0 >= len) v.x = 0.f;
                if (c + 1 >= len) v.y = 0.f;
                if (c + 2 >= len) v.z = 0.f;
                if (c + 3 >= len) v.w = 0.f;
            }
            *reinterpret_cast<float4*>(&sx[r][c4 * 4]) = v;
        }
        __syncthreads();

        // groups pull rows dynamically from the smem queue
        while (true) {
            int myrow;
            if ((lane & 15) == 0) myrow = atomicAdd(&s_next, 1);
            myrow = __shfl_sync(gmask, myrow, gsrc);
            if (myrow >= cnt) break;

            const int len = slen[myrow];
            if (len > 0) {
                const int row = base + myrow;
                const int len4 = (len + 3) & ~3;
                const float4* Wr = reinterpret_cast<const float4*>(W)
                                   + (size_t)row * 1024 + t;
                const float* xr = sx[myrow];

                float4 acc = make_float4(0.f, 0.f, 0.f, 0.f);

                #pragma unroll 1
                for (int i = 0; i < len4; i += 4) {
                    float4 w0 = Wr[(i + 0) * 16];
                    float4 w1 = Wr[(i + 1) * 16];
                    float4 w2 = Wr[(i + 2) * 16];
                    float4 w3 = Wr[(i + 3) * 16];
                    float4 xv = *reinterpret_cast<const float4*>(xr + i);
                    acc.x += xv.x * w0.x + xv.y * w1.x + xv.z * w2.x + xv.w * w3.x;
                    acc.y += xv.x * w0.y + xv.y * w1.y + xv.z * w2.y + xv.w * w3.y;
                    acc.z += xv.x * w0.z + xv.y * w1.z + xv.z * w2.z + xv.w * w3.z;
                    acc.w += xv.x * w0.w + xv.y * w1.w + xv.z * w2.w + xv.w * w3.w;
                }

                float4 bb = reinterpret_cast<const float4*>(b)[(size_t)row * 16 + t];
                float4 r4;
                r4.x = gelu_tanh(acc.x + bb.x);
                r4.y = gelu_tanh(acc.y + bb.y);
                r4.z = gelu_tanh(acc.z + bb.z);
                r4.w = gelu_tanh(acc.w + bb.w);
                reinterpret_cast<float4*>(out)[(size_t)row * 16 + t] = r4;
            }
        }
        __syncthreads();   // protect sx before next chunk overwrites it
    }
}

extern "C" void kernel_launch(void* const* d_in, const int* in_sizes, int n_in,
                              void* d_out, int out_size) {
    const float* seg     = (const float*)d_in[0];
    const float* W       = (const float*)d_in[1];
    const float* b       = (const float*)d_in[2];
    const int*   lengths = (const int*)d_in[3];
    float* out = (float*)d_out;

    int n = in_sizes[3];

    k_reset<<<1, 1>>>();
    fe_kernel<<<NBLOCKS, THREADS>>>(seg, W, b, lengths, out, n);
}

// round 10
// speedup vs baseline: 1.1820x; 1.1820x over previous
#include <cuda_runtime.h>
#include <math.h>

#define MAX_IN 64
#define D_MODEL 64
#define ROWS_PER_BLOCK 16
#define THREADS 256
#define CAP 1024                 // rows per bucket
#define BUCKETS 64
#define BPB (CAP / ROWS_PER_BLOCK)          // 64 blocks per bucket
#define BUCKET_GRID (BUCKETS * BPB)         // 4096
#define MAXN (1 << 17)

__device__ int g_bucket[BUCKETS * CAP];
__device__ int g_cnt[BUCKETS + 1];
__device__ int g_overflow[MAXN];
__device__ int g_ovf;

__device__ __forceinline__ float fast_tanh(float x) {
    float y;
    asm("tanh.approx.f32 %0, %1;" : "=f"(y) : "f"(x));
    return y;
}

__device__ __forceinline__ float gelu_tanh(float v) {
    const float c = 0.7978845608028654f;
    float u = c * (v + 0.044715f * v * v * v);
    return 0.5f * v * (1.0f + fast_tanh(u));
}

// ---------- prepass ----------
__global__ void k_zero() {
    int t = threadIdx.x;
    if (t <= BUCKETS) g_cnt[t] = 0;
    if (t == BUCKETS + 1) g_ovf = 0;
}

// fused: block-local histogram -> one range-reserve atomic per length -> scatter
__global__ void k_scatter(const int* __restrict__ lengths, int n) {
    __shared__ int h[BUCKETS + 1];
    __shared__ int bbase[BUCKETS + 1];
    int tid = threadIdx.x;
    if (tid <= BUCKETS) h[tid] = 0;
    __syncthreads();
    int r = blockIdx.x * blockDim.x + tid;
    int len = 0, rank = 0;
    if (r < n) {
        len = lengths[r];
        len = max(1, min(64, len));
        rank = atomicAdd(&h[len], 1);
    }
    __syncthreads();
    if (tid <= BUCKETS && h[tid] > 0) bbase[tid] = atomicAdd(&g_cnt[tid], h[tid]);
    __syncthreads();
    if (r < n) {
        int pos = bbase[len] + rank;
        if (pos < CAP) {
            g_bucket[(len - 1) * CAP + pos] = r;
        } else {
            int o = atomicAdd(&g_ovf, 1);
            g_overflow[o] = r;
        }
    }
}

// ---------- main kernel ----------
__global__ __launch_bounds__(THREADS, 6)
void fe_kernel(const float* __restrict__ seg,
               const float* __restrict__ W,
               const float* __restrict__ b,
               const int*   __restrict__ lengths,
               float* __restrict__ out,
               int n)
{
    __shared__ float sx[ROWS_PER_BLOCK][MAX_IN];
    __shared__ int   slen[ROWS_PER_BLOCK];
    __shared__ int   sidx[ROWS_PER_BLOCK];

    const int tid = threadIdx.x;

    if (blockIdx.x < BUCKET_GRID) {
        // bucket blocks: bucket 0 = len 64 (longest first)
        int bucket = blockIdx.x >> 6;
        int slot   = blockIdx.x & 63;
        int len    = BUCKETS - bucket;
        int cnt    = min(g_cnt[len], CAP);
        int start  = slot * ROWS_PER_BLOCK;
        if (start >= cnt) return;
        if (tid < ROWS_PER_BLOCK) {
            int r = start + tid;
            if (r < cnt) {
                sidx[tid] = g_bucket[(len - 1) * CAP + r];
                slen[tid] = len;
            } else {
                sidx[tid] = 0;
                slen[tid] = 0;
            }
        }
    } else {
        // overflow blocks (normally all-empty)
        int j = blockIdx.x - BUCKET_GRID;
        int cnt = g_ovf;
        int start = j * ROWS_PER_BLOCK;
        if (start >= cnt) return;
        if (tid < ROWS_PER_BLOCK) {
            int r = start + tid;
            if (r < cnt) {
                int src = g_overflow[r];
                sidx[tid] = src;
                slen[tid] = lengths[src];
            } else {
                sidx[tid] = 0;
                slen[tid] = 0;
            }
        }
    }
    __syncthreads();

    // Cooperative masked load of x rows into smem
    {
        int r  = tid >> 4;
        int c4 = tid & 15;
        float4 v = make_float4(0.f, 0.f, 0.f, 0.f);
        int len = slen[r];
        if (len > 0) {
            int src = sidx[r];
            v = reinterpret_cast<const float4*>(seg)[(size_t)src * 16 + c4];
            int c = c4 * 4;
            if (c + 0 >= len) v.x = 0.f;
            if (c + 1 >= len) v.y = 0.f;
            if (c + 2 >= len) v.z = 0.f;
            if (c + 3 >= len) v.w = 0.f;
        }
        *reinterpret_cast<float4*>(&sx[r][c4 * 4]) = v;
    }
    __syncthreads();

    const int g = tid >> 4;
    const int t = tid & 15;
    const int len = slen[g];
    if (len == 0) return;
    const int src = sidx[g];

    const int len4 = (len + 3) & ~3;
    const float4* Wr = reinterpret_cast<const float4*>(W) + (size_t)src * 1024 + t;
    const float* xr = sx[g];

    float4 acc = make_float4(0.f, 0.f, 0.f, 0.f);

    #pragma unroll 1
    for (int i = 0; i < len4; i += 4) {
        float4 w0 = Wr[(i + 0) * 16];
        float4 w1 = Wr[(i + 1) * 16];
        float4 w2 = Wr[(i + 2) * 16];
        float4 w3 = Wr[(i + 3) * 16];
        float4 xv = *reinterpret_cast<const float4*>(xr + i);
        acc.x += xv.x * w0.x + xv.y * w1.x + xv.z * w2.x + xv.w * w3.x;
        acc.y += xv.x * w0.y + xv.y * w1.y + xv.z * w2.y + xv.w * w3.y;
        acc.z += xv.x * w0.z + xv.y * w1.z + xv.z * w2.z + xv.w * w3.z;
        acc.w += xv.x * w0.w + xv.y * w1.w + xv.z * w2.w + xv.w * w3.w;
    }

    float4 bb = reinterpret_cast<const float4*>(b)[(size_t)src * 16 + t];
    float4 r4;
    r4.x = gelu_tanh(acc.x + bb.x);
    r4.y = gelu_tanh(acc.y + bb.y);
    r4.z = gelu_tanh(acc.z + bb.z);
    r4.w = gelu_tanh(acc.w + bb.w);

    reinterpret_cast<float4*>(out)[(size_t)src * 16 + t] = r4;
}

extern "C" void kernel_launch(void* const* d_in, const int* in_sizes, int n_in,
                              void* d_out, int out_size) {
    const float* seg     = (const float*)d_in[0];
    const float* W       = (const float*)d_in[1];
    const float* b       = (const float*)d_in[2];
    const int*   lengths = (const int*)d_in[3];
    float* out = (float*)d_out;

    int n = in_sizes[3];
    if (n > MAXN) n = MAXN;   // static scratch bound (N=50000 actual)

    int sgrid = (n + THREADS - 1) / THREADS;
    int ovf_grid = (n + ROWS_PER_BLOCK - 1) / ROWS_PER_BLOCK;

    k_zero<<<1, 128>>>();
    k_scatter<<<sgrid, THREADS>>>(lengths, n);
    fe_kernel<<<BUCKET_GRID + ovf_grid, THREADS>>>(seg, W, b, lengths, out, n);
}